// round 5
// baseline (speedup 1.0000x reference)
#include <cuda_runtime.h>
#include <stdint.h>
#include <math.h>

// ---------------------------------------------------------------------------
// JAX threefry2x32 (key = (0,1) from jax.random.key(1)), partitionable mode:
// bits[j] = out0 ^ out1 of threefry2x32((0,1), (hi=0, lo=j))
// ---------------------------------------------------------------------------
__device__ __forceinline__ uint32_t rotl32(uint32_t x, int r) {
    return (x << r) | (x >> (32 - r));
}

__device__ __forceinline__ uint32_t jax_bits(uint32_t j) {
    uint32_t x0 = 0u, x1 = j;
    const uint32_t ks0 = 0u, ks1 = 1u, ks2 = 0x1BD11BDBu; // 0^1^0x1BD11BDA
    x0 += ks0; x1 += ks1;
#define TF_R(r) { x0 += x1; x1 = rotl32(x1, (r)); x1 ^= x0; }
    TF_R(13) TF_R(15) TF_R(26) TF_R(6)
    x0 += ks1; x1 += ks2 + 1u;
    TF_R(17) TF_R(29) TF_R(16) TF_R(24)
    x0 += ks2; x1 += ks0 + 2u;
    TF_R(13) TF_R(15) TF_R(26) TF_R(6)
    x0 += ks0; x1 += ks1 + 3u;
    TF_R(17) TF_R(29) TF_R(16) TF_R(24)
    x0 += ks1; x1 += ks2 + 4u;
    TF_R(13) TF_R(15) TF_R(26) TF_R(6)
    x0 += ks2; x1 += ks0 + 5u;
#undef TF_R
    return x0 ^ x1;
}

__device__ __forceinline__ float jax_gumbel(uint32_t j) {
    uint32_t bits = jax_bits(j);
    float f = __uint_as_float((bits >> 9) | 0x3f800000u) - 1.0f; // [0,1)
    const float TINY = 1.1754943508222875e-38f;
    float u = fmaxf(TINY, f + TINY);   // uniform(minval=tiny, maxval=1)
    return -logf(-logf(u));
}

// Bilinear 4->8 (jax.image.resize 'bilinear' == half-pixel, edge-renormalized
// which reduces to clamped taps): even v: 0.25*in[j-1] + 0.75*in[j],
// odd v: 0.75*in[j] + 0.25*in[j+1], j = v/2, indices clamped to [0,3].
__device__ __forceinline__ void lin_coef(int v, int& a, int& b, float& wa, float& wb) {
    int j = v >> 1;
    if ((v & 1) == 0) { a = j - 1; b = j;     wa = 0.25f; wb = 0.75f; }
    else              { a = j;     b = j + 1; wa = 0.75f; wb = 0.25f; }
    a = max(0, min(3, a));
    b = max(0, min(3, b));
}

// ---------------------------------------------------------------------------
// One block per batch. 512 threads.
//   Phase 1: channel max over C=1024 (coalesced float4 stream of x[b], 256KB)
//   Phase 2: tiny gate computation fully in smem
//   Phase 3: out = relu(x * gate) (re-read x[b] — expected L2-resident)
// ---------------------------------------------------------------------------
__global__ void __launch_bounds__(512, 3)
sa_layer_kernel(const float* __restrict__ x,
                const float* __restrict__ w1,   // [1,1,3,3] -> 9
                const float* __restrict__ w5,   // [4,2,3,3] -> 72
                const float* __restrict__ b5,   // 4
                const float* __restrict__ w6,   // [1,4,3,3] -> 36
                const float* __restrict__ b6,   // 1
                float* __restrict__ out)
{
    extern __shared__ float sm[];
    float* red  = sm;          // 2048 floats (512 x float4 reduction buf)
    float* msh  = sm + 2048;   // 64  : channel max m[8][8]
    float* c0   = sm + 2112;   // 16  : pooled 4x4
    float* c1   = sm + 2128;   // 16  : after 3x3 conv
    float* up   = sm + 2144;   // 64  : bilinear upsample 8x8
    float* hsh  = sm + 2208;   // 256 : conv5 output [4][64]
    float* gate = sm + 2464;   // 64
    float* ws   = sm + 2528;   // 122 : w1[0..8] w5[9..80] b5[81..84] w6[85..120] b6[121]

    const int t = threadIdx.x;
    const int b = blockIdx.x;
    const float4* xb = (const float4*)(x + (size_t)b * 65536);

    // load weights into smem (done by first 122 threads, covered by sync below)
    if (t < 9)        ws[t] = w1[t];
    else if (t < 81)  ws[t] = w5[t - 9];
    else if (t < 85)  ws[t] = b5[t - 81];
    else if (t < 121) ws[t] = w6[t - 85];
    else if (t == 121) ws[121] = b6[0];

    // ---- Phase 1: channel max ------------------------------------------------
    // float4 index = it*512 + t; pixel-group (4 pixels) = t & 15 (constant per thread)
    float4 vmax = make_float4(-INFINITY, -INFINITY, -INFINITY, -INFINITY);
#pragma unroll 4
    for (int it = 0; it < 32; ++it) {
        float4 v = __ldg(&xb[it * 512 + t]);
        vmax.x = fmaxf(vmax.x, v.x);
        vmax.y = fmaxf(vmax.y, v.y);
        vmax.z = fmaxf(vmax.z, v.z);
        vmax.w = fmaxf(vmax.w, v.w);
    }
    ((float4*)red)[t] = vmax;
    __syncthreads();

    if (t < 64) {  // t = pixel p
        int g = t >> 2, c = t & 3;
        float mv = -INFINITY;
#pragma unroll 8
        for (int i = 0; i < 32; ++i)
            mv = fmaxf(mv, red[(g + 16 * i) * 4 + c]);  // == red[p + 64*i]
        msh[t] = mv;
    }
    __syncthreads();

    // ---- Phase 2a: 2x2 windows + probabilistic pool (16 threads) -------------
    if (t < 16) {
        int wy = t >> 2, wx = t & 3;
        float win[4];
        win[0] = msh[(2 * wy) * 8 + 2 * wx];
        win[1] = msh[(2 * wy) * 8 + 2 * wx + 1];
        win[2] = msh[(2 * wy + 1) * 8 + 2 * wx];
        win[3] = msh[(2 * wy + 1) * 8 + 2 * wx + 1];
        float winc[4];
#pragma unroll
        for (int k = 0; k < 4; ++k) {
            float v = win[k];
            winc[k] = (isnan(v) || isinf(v) || v < 0.0f) ? 1e-8f : v;
        }
        // gumbel-max categorical; flat index j = b*64 + w*4 + k (shape 512,1,16,4)
        uint32_t base = (uint32_t)(b * 64 + t * 4);
        float best = -INFINITY; int arg = 0;
#pragma unroll
        for (int k = 0; k < 4; ++k) {
            float val = winc[k] + jax_gumbel(base + (uint32_t)k);
            if (val > best) { best = val; arg = k; }  // first-max, like jnp.argmax
        }
        float mo2 = winc[arg];
        float mo3 = fmaxf(fmaxf(win[0], win[1]), fmaxf(win[2], win[3]));
        float ao4 = (win[0] + win[1] + win[2] + win[3]) * 0.25f;
        c0[t] = 0.1f * mo2 + 0.6f * mo3 + 0.3f * ao4;
    }
    __syncthreads();

    // ---- Phase 2b: 3x3 conv (bias-free) on 4x4, zero pad ---------------------
    if (t < 16) {
        int y = t >> 2, xx = t & 3;
        float acc = 0.0f;
#pragma unroll
        for (int dy = 0; dy < 3; ++dy) {
#pragma unroll
            for (int dx = 0; dx < 3; ++dx) {
                int yy = y + dy - 1, xc = xx + dx - 1;
                if (yy >= 0 && yy < 4 && xc >= 0 && xc < 4)
                    acc += c0[yy * 4 + xc] * ws[dy * 3 + dx];
            }
        }
        c1[t] = acc;
    }
    __syncthreads();

    // ---- Phase 2c: bilinear upsample 4->8 (64 threads) -----------------------
    if (t < 64) {
        int y = t >> 3, xx = t & 7;
        int ya, yb2, xa, xb2; float wya, wyb, wxa, wxb;
        lin_coef(y, ya, yb2, wya, wyb);
        lin_coef(xx, xa, xb2, wxa, wxb);
        up[t] = wya * (wxa * c1[ya * 4 + xa] + wxb * c1[ya * 4 + xb2]) +
                wyb * (wxa * c1[yb2 * 4 + xa] + wxb * c1[yb2 * 4 + xb2]);
    }
    __syncthreads();

    // ---- Phase 2d: conv5 (2->4 ch, 3x3) + relu (256 threads) -----------------
    if (t < 256) {
        int o = t >> 6, p = t & 63, y = p >> 3, xx = p & 7;
        float acc = ws[81 + o];
#pragma unroll
        for (int dy = 0; dy < 3; ++dy) {
#pragma unroll
            for (int dx = 0; dx < 3; ++dx) {
                int yy = y + dy - 1, xc = xx + dx - 1;
                if (yy >= 0 && yy < 8 && xc >= 0 && xc < 8) {
                    int pp = yy * 8 + xc;
                    acc += msh[pp] * ws[9 + ((o * 2 + 0) * 3 + dy) * 3 + dx];
                    acc += up[pp]  * ws[9 + ((o * 2 + 1) * 3 + dy) * 3 + dx];
                }
            }
        }
        hsh[o * 64 + p] = fmaxf(acc, 0.0f);
    }
    __syncthreads();

    // ---- Phase 2e: conv6 (4->1 ch, 3x3) + sigmoid (64 threads) ---------------
    if (t < 64) {
        int y = t >> 3, xx = t & 7;
        float acc = ws[121];
#pragma unroll
        for (int o = 0; o < 4; ++o) {
#pragma unroll
            for (int dy = 0; dy < 3; ++dy) {
#pragma unroll
                for (int dx = 0; dx < 3; ++dx) {
                    int yy = y + dy - 1, xc = xx + dx - 1;
                    if (yy >= 0 && yy < 8 && xc >= 0 && xc < 8)
                        acc += hsh[o * 64 + yy * 8 + xc] * ws[85 + (o * 3 + dy) * 3 + dx];
                }
            }
        }
        gate[t] = 1.0f / (1.0f + expf(-acc));
    }
    __syncthreads();

    // ---- Phase 3: out = relu(x * gate) --------------------------------------
    int p0 = (t & 15) * 4;
    float4 g4 = make_float4(gate[p0], gate[p0 + 1], gate[p0 + 2], gate[p0 + 3]);
    float4* ob = (float4*)(out + (size_t)b * 65536);
#pragma unroll 4
    for (int it = 0; it < 32; ++it) {
        float4 v = __ldcs(&xb[it * 512 + t]);   // last use: evict-first
        v.x = fmaxf(v.x * g4.x, 0.0f);
        v.y = fmaxf(v.y * g4.y, 0.0f);
        v.z = fmaxf(v.z * g4.z, 0.0f);
        v.w = fmaxf(v.w * g4.w, 0.0f);
        __stcs(&ob[it * 512 + t], v);           // streaming store: don't pollute L2
    }
}

extern "C" void kernel_launch(void* const* d_in, const int* in_sizes, int n_in,
                              void* d_out, int out_size) {
    const float* x  = (const float*)d_in[0];
    const float* w1 = (const float*)d_in[1];
    const float* w5 = (const float*)d_in[2];
    const float* b5 = (const float*)d_in[3];
    const float* w6 = (const float*)d_in[4];
    const float* b6 = (const float*)d_in[5];
    float* out = (float*)d_out;

    // ~10.4 KB actually used; request 60 KB to cap occupancy at 3 CTAs/SM so the
    // phase-3 re-read of x[b] stays L2-resident (reuse distance ~111 MB < 126 MB).
    const int smem_bytes = 61440;
    cudaFuncSetAttribute(sa_layer_kernel,
                         cudaFuncAttributeMaxDynamicSharedMemorySize, smem_bytes);
    sa_layer_kernel<<<512, 512, smem_bytes>>>(x, w1, w5, b5, w6, b6, out);
}